// round 1
// baseline (speedup 1.0000x reference)
#include <cuda_runtime.h>

// Problem dims
#define SEQ   256
#define BATCH 32
#define INF   1024
#define HID   1024
#define MTOT  (SEQ * BATCH)        // 8192 rows
#define BH    (BATCH * HID)        // 32768

// Scratch (device globals — no allocation allowed)
__device__ float g_lin[MTOT * HID];   // 32 MB, reused for layer0 and layer1 lin
__device__ float g_y0 [MTOT * HID];   // 32 MB, layer0 output

// ---------------------------------------------------------------------------
// SGEMM: C[m,n] = sum_k A[m,k] * W[n,k] + bias[n]
// A: row-major [M,K], W: row-major [N,K]  (i.e. C = A * W^T + b)
// Classic 128x128x8 tile, 256 threads, 8x8 per-thread register block.
// ---------------------------------------------------------------------------
#define BM 128
#define BN 128
#define BK 8
#define TM 8
#define TN 8

__global__ __launch_bounds__(256, 2)
void gemm_abt_bias(const float* __restrict__ A,
                   const float* __restrict__ W,
                   const float* __restrict__ bias,
                   float* __restrict__ C,
                   int M, int N, int K)
{
    __shared__ float As[BK][BM];   // As[k][m]
    __shared__ float Bs[BK][BN];   // Bs[k][n]

    const int tid = threadIdx.x;
    const int m0 = blockIdx.y * BM;
    const int n0 = blockIdx.x * BN;

    // Loader mapping: 256 threads, each loads one float4 per tile per matrix.
    // Tile is 128 rows x 8 k -> 2 float4 per row -> row = tid/2, kq = (tid&1)*4
    const int lrow = tid >> 1;
    const int lk   = (tid & 1) * 4;

    // Compute mapping: 16x16 threads, 8x8 regs each
    const int tr = (tid >> 4) * TM;   // row offset in tile
    const int tc = (tid & 15) * TN;   // col offset in tile

    float acc[TM][TN];
    #pragma unroll
    for (int i = 0; i < TM; i++)
        #pragma unroll
        for (int j = 0; j < TN; j++)
            acc[i][j] = 0.0f;

    for (int k0 = 0; k0 < K; k0 += BK) {
        // Load A tile: A[m0+lrow][k0+lk .. +3]
        float4 av = *reinterpret_cast<const float4*>(&A[(size_t)(m0 + lrow) * K + k0 + lk]);
        As[lk + 0][lrow] = av.x;
        As[lk + 1][lrow] = av.y;
        As[lk + 2][lrow] = av.z;
        As[lk + 3][lrow] = av.w;
        // Load W tile: W[n0+lrow][k0+lk .. +3]
        float4 bv = *reinterpret_cast<const float4*>(&W[(size_t)(n0 + lrow) * K + k0 + lk]);
        Bs[lk + 0][lrow] = bv.x;
        Bs[lk + 1][lrow] = bv.y;
        Bs[lk + 2][lrow] = bv.z;
        Bs[lk + 3][lrow] = bv.w;
        __syncthreads();

        #pragma unroll
        for (int k = 0; k < BK; k++) {
            float ra[TM], rb[TN];
            #pragma unroll
            for (int i = 0; i < TM; i++) ra[i] = As[k][tr + i];
            #pragma unroll
            for (int j = 0; j < TN; j++) rb[j] = Bs[k][tc + j];
            #pragma unroll
            for (int i = 0; i < TM; i++)
                #pragma unroll
                for (int j = 0; j < TN; j++)
                    acc[i][j] = fmaf(ra[i], rb[j], acc[i][j]);
        }
        __syncthreads();
    }

    // Epilogue: add bias, store
    #pragma unroll
    for (int i = 0; i < TM; i++) {
        float* crow = &C[(size_t)(m0 + tr + i) * N + n0 + tc];
        #pragma unroll
        for (int j = 0; j < TN; j += 4) {
            float4 v;
            v.x = acc[i][j + 0] + bias[n0 + tc + j + 0];
            v.y = acc[i][j + 1] + bias[n0 + tc + j + 1];
            v.z = acc[i][j + 2] + bias[n0 + tc + j + 2];
            v.w = acc[i][j + 3] + bias[n0 + tc + j + 3];
            *reinterpret_cast<float4*>(&crow[j]) = v;
        }
    }
}

// ---------------------------------------------------------------------------
// IndRNN scan: for each (b,h):  h_s = relu(lin[s] + r[h]*h_{s-1}), y[s]=h_s
// 32768 threads total, serial over SEQ. Final h written to hid_out[b*2H + off + h].
// ---------------------------------------------------------------------------
__global__ __launch_bounds__(256)
void indrnn_scan(const float* __restrict__ lin,
                 const float* __restrict__ rec,      // r[HID] for this layer
                 float* __restrict__ y,              // (SEQ, B, H)
                 float* __restrict__ hid_out,        // (B, 2*HID) base
                 int layer_off)                      // 0 or HID
{
    const int idx = blockIdx.x * blockDim.x + threadIdx.x;   // b*HID + h
    const int h = idx & (HID - 1);
    const int b = idx >> 10;
    const float r = rec[h];

    float hv = 0.0f;
    #pragma unroll 4
    for (int s = 0; s < SEQ; s++) {
        float v = lin[(size_t)s * BH + idx];
        hv = fmaxf(fmaf(r, hv, v), 0.0f);
        y[(size_t)s * BH + idx] = hv;
    }
    hid_out[(size_t)b * (2 * HID) + layer_off + h] = hv;
}

// ---------------------------------------------------------------------------
// kernel_launch
// Inputs (metadata order): x (S,B,IN), w0 (HID,IN), b0 (HID), w1 (HID,HID),
//                          b1 (HID), rec (2,HID)
// Output: y1 (S,B,HID) flattened, then hiddens (B, 2*HID)
// ---------------------------------------------------------------------------
extern "C" void kernel_launch(void* const* d_in, const int* in_sizes, int n_in,
                              void* d_out, int out_size)
{
    const float* x   = (const float*)d_in[0];
    const float* w0  = (const float*)d_in[1];
    const float* b0  = (const float*)d_in[2];
    const float* w1  = (const float*)d_in[3];
    const float* b1  = (const float*)d_in[4];
    const float* rec = (const float*)d_in[5];

    float* out    = (float*)d_out;
    float* y1_out = out;                        // SEQ*BATCH*HID floats
    float* hid_out = out + (size_t)MTOT * HID;  // BATCH * 2*HID floats

    float* lin;
    float* y0;
    cudaGetSymbolAddress((void**)&lin, g_lin);
    cudaGetSymbolAddress((void**)&y0,  g_y0);

    dim3 ggrid(HID / BN, MTOT / BM);   // (8, 64)
    dim3 gblk(256);
    dim3 sgrid(BH / 256);              // 128
    dim3 sblk(256);

    // Layer 0
    gemm_abt_bias<<<ggrid, gblk>>>(x, w0, b0, lin, MTOT, HID, INF);
    indrnn_scan<<<sgrid, sblk>>>(lin, rec, y0, hid_out, 0);

    // Layer 1
    gemm_abt_bias<<<ggrid, gblk>>>(y0, w1, b1, lin, MTOT, HID, HID);
    indrnn_scan<<<sgrid, sblk>>>(lin, rec + HID, y1_out, hid_out, HID);
}

// round 4
// speedup vs baseline: 2.6931x; 2.6931x over previous
#include <cuda_runtime.h>
#include <cuda_bf16.h>
#include <cstdint>

// Problem dims
#define SEQ   256
#define BATCH 32
#define HIDN  1024
#define KDIM  1024
#define MTOT  (SEQ * BATCH)        // 8192
#define BH    (BATCH * HIDN)       // 32768

// ---------------------------------------------------------------------------
// Device-global scratch (no allocation allowed)
// ---------------------------------------------------------------------------
__device__ __align__(16) __nv_bfloat16 g_Ahi[MTOT * KDIM];   // 16 MB
__device__ __align__(16) __nv_bfloat16 g_Alo[MTOT * KDIM];   // 16 MB
__device__ __align__(16) __nv_bfloat16 g_Whi[HIDN * KDIM];   // 2 MB
__device__ __align__(16) __nv_bfloat16 g_Wlo[HIDN * KDIM];   // 2 MB
__device__ __align__(16) float         g_lin[MTOT * HIDN];   // 32 MB

// ---------------------------------------------------------------------------
// PTX helpers (base sm_103 features only: cp.async, ldmatrix, mma.sync)
// ---------------------------------------------------------------------------
__device__ __forceinline__ uint32_t smem_to_u32(const void* p) {
    uint32_t a;
    asm("{ .reg .u64 t; cvta.to.shared.u64 t, %1; cvt.u32.u64 %0, t; }" : "=r"(a) : "l"(p));
    return a;
}

__device__ __forceinline__ void cp16(uint32_t s, const void* g) {
    asm volatile("cp.async.cg.shared.global [%0], [%1], 16;" :: "r"(s), "l"(g));
}
#define CP_COMMIT() asm volatile("cp.async.commit_group;" ::: "memory")
#define CP_WAIT0()  asm volatile("cp.async.wait_group 0;" ::: "memory")
#define CP_WAIT1()  asm volatile("cp.async.wait_group 1;" ::: "memory")

__device__ __forceinline__ void ldsm4(uint32_t& r0, uint32_t& r1, uint32_t& r2,
                                      uint32_t& r3, uint32_t addr) {
    asm volatile("ldmatrix.sync.aligned.m8n8.x4.shared.b16 {%0,%1,%2,%3}, [%4];"
        : "=r"(r0), "=r"(r1), "=r"(r2), "=r"(r3) : "r"(addr));
}

__device__ __forceinline__ void mma16816(float* c, const uint32_t* a, const uint32_t* b) {
    asm volatile(
        "mma.sync.aligned.m16n8k16.row.col.f32.bf16.bf16.f32 "
        "{%0,%1,%2,%3}, {%4,%5,%6,%7}, {%8,%9}, {%0,%1,%2,%3};"
        : "+f"(c[0]), "+f"(c[1]), "+f"(c[2]), "+f"(c[3])
        : "r"(a[0]), "r"(a[1]), "r"(a[2]), "r"(a[3]), "r"(b[0]), "r"(b[1]));
}

// ---------------------------------------------------------------------------
// Split fp32 -> bf16 hi + lo (vectorized by 4)
// ---------------------------------------------------------------------------
__global__ __launch_bounds__(256)
void split_fp32_bf16(const float* __restrict__ in,
                     __nv_bfloat16* __restrict__ hi,
                     __nv_bfloat16* __restrict__ lo, int n4)
{
    int i = blockIdx.x * blockDim.x + threadIdx.x;
    if (i >= n4) return;
    float4 v = reinterpret_cast<const float4*>(in)[i];
    float f[4] = {v.x, v.y, v.z, v.w};
    union { __nv_bfloat16 b[4]; uint2 u; } H, L;
#pragma unroll
    for (int j = 0; j < 4; j++) {
        __nv_bfloat16 h = __float2bfloat16(f[j]);
        H.b[j] = h;
        L.b[j] = __float2bfloat16(f[j] - __bfloat162float(h));
    }
    reinterpret_cast<uint2*>(hi)[i] = H.u;
    reinterpret_cast<uint2*>(lo)[i] = L.u;
}

// ---------------------------------------------------------------------------
// mma.sync bf16-split GEMM: C[m,n] = sum_k A[m,k]*W[n,k] + bias[n]
// A ~ Ahi+Alo, W ~ Whi+Wlo. acc += Ahi*Whi + Ahi*Wlo + Alo*Whi (fp32 regs).
// CTA tile 128x128, K-stage 32, double-buffered cp.async.
// 8 warps: warp tile 64(m) x 32(n); per warp 4 m-tiles(16) x 4 n-tiles(8).
// Smem rows padded to 80B -> ldmatrix conflict-free (80*r mod 128 distinct).
// ---------------------------------------------------------------------------
#define PITCH       80
#define TILE_BYTES  (128 * PITCH)             // 10240
#define STAGE_BYTES (4 * TILE_BYTES)          // 40960
#define GEMM_SMEM   (2 * STAGE_BYTES)         // 81920
#define NK          (KDIM / 32)               // 32 stages

__device__ __forceinline__ void load_stage(uint32_t sb, int buf, int s,
                                           const __nv_bfloat16* __restrict__ Ahi,
                                           const __nv_bfloat16* __restrict__ Alo,
                                           const __nv_bfloat16* __restrict__ Whi,
                                           const __nv_bfloat16* __restrict__ Wlo,
                                           int m0, int n0, int tid)
{
    const int kc = s * 32;
    const uint32_t base = sb + buf * STAGE_BYTES;
#pragma unroll
    for (int it = 0; it < 2; it++) {
        int t = tid + it * 256;          // 0..511
        int row = t >> 2;
        int ch = t & 3;
        uint32_t soff = (uint32_t)(row * PITCH + ch * 16);
        size_t goffA = (size_t)(m0 + row) * KDIM + kc + ch * 8;
        size_t goffW = (size_t)(n0 + row) * KDIM + kc + ch * 8;
        cp16(base + 0 * TILE_BYTES + soff, Ahi + goffA);
        cp16(base + 1 * TILE_BYTES + soff, Alo + goffA);
        cp16(base + 2 * TILE_BYTES + soff, Whi + goffW);
        cp16(base + 3 * TILE_BYTES + soff, Wlo + goffW);
    }
}

__global__ __launch_bounds__(256)
void gemm_mma_split(const __nv_bfloat16* __restrict__ Ahi,
                    const __nv_bfloat16* __restrict__ Alo,
                    const __nv_bfloat16* __restrict__ Whi,
                    const __nv_bfloat16* __restrict__ Wlo,
                    const float* __restrict__ bias,
                    float* __restrict__ C)
{
    extern __shared__ __align__(16) char smem[];
    const uint32_t sb = smem_to_u32(smem);
    const int tid = threadIdx.x;
    const int wid = tid >> 5;
    const int lane = tid & 31;
    const int m0 = blockIdx.y * 128;
    const int n0 = blockIdx.x * 128;
    const int wm = (wid >> 2) * 64;      // warp row offset in tile
    const int wn = (wid & 3) * 32;       // warp col offset in tile

    float acc[4][4][4];
#pragma unroll
    for (int i = 0; i < 4; i++)
#pragma unroll
        for (int j = 0; j < 4; j++)
#pragma unroll
            for (int r = 0; r < 4; r++) acc[i][j][r] = 0.0f;

    // ldmatrix lane addressing (fixed per thread)
    const int a_row = lane & 15;           // + wm + mi*16
    const int a_ch  = lane >> 4;           // 16B chunk within k16
    const int b_row = (lane & 7) + ((lane >> 4) << 3);  // + wn + half*16
    const int b_ch  = (lane >> 3) & 1;

    load_stage(sb, 0, 0, Ahi, Alo, Whi, Wlo, m0, n0, tid);
    CP_COMMIT();

    for (int s = 0; s < NK; s++) {
        if (s + 1 < NK) {
            load_stage(sb, (s + 1) & 1, s + 1, Ahi, Alo, Whi, Wlo, m0, n0, tid);
            CP_COMMIT();
            CP_WAIT1();
        } else {
            CP_WAIT0();
        }
        __syncthreads();

        const uint32_t st = sb + (s & 1) * STAGE_BYTES;
#pragma unroll
        for (int kk = 0; kk < 2; kk++) {
            // B fragments: 4 n8-tiles (two x4 loads each for hi and lo)
            uint32_t bhi[4][2], blo[4][2];
#pragma unroll
            for (int half = 0; half < 2; half++) {
                uint32_t boff = (uint32_t)((wn + b_row + half * 16) * PITCH
                                           + (kk * 2 + b_ch) * 16);
                ldsm4(bhi[half * 2][0], bhi[half * 2][1],
                      bhi[half * 2 + 1][0], bhi[half * 2 + 1][1],
                      st + 2 * TILE_BYTES + boff);
                ldsm4(blo[half * 2][0], blo[half * 2][1],
                      blo[half * 2 + 1][0], blo[half * 2 + 1][1],
                      st + 3 * TILE_BYTES + boff);
            }
#pragma unroll
            for (int mi = 0; mi < 4; mi++) {
                uint32_t aoff = (uint32_t)((wm + mi * 16 + a_row) * PITCH
                                           + (kk * 2 + a_ch) * 16);
                uint32_t ahi[4], alo[4];
                ldsm4(ahi[0], ahi[1], ahi[2], ahi[3], st + 0 * TILE_BYTES + aoff);
                ldsm4(alo[0], alo[1], alo[2], alo[3], st + 1 * TILE_BYTES + aoff);
#pragma unroll
                for (int ni = 0; ni < 4; ni++) {
                    mma16816(acc[mi][ni], ahi, bhi[ni]);
                    mma16816(acc[mi][ni], ahi, blo[ni]);
                    mma16816(acc[mi][ni], alo, bhi[ni]);
                }
            }
        }
        __syncthreads();
    }

    // Epilogue: add bias, store fp32
    const int er = lane >> 2;
    const int ec = (lane & 3) * 2;
#pragma unroll
    for (int mi = 0; mi < 4; mi++) {
        const int r = m0 + wm + mi * 16 + er;
#pragma unroll
        for (int ni = 0; ni < 4; ni++) {
            const int c = n0 + wn + ni * 8 + ec;
            const float b0 = __ldg(bias + c);
            const float b1 = __ldg(bias + c + 1);
            float2 v0 = {acc[mi][ni][0] + b0, acc[mi][ni][1] + b1};
            float2 v1 = {acc[mi][ni][2] + b0, acc[mi][ni][3] + b1};
            *reinterpret_cast<float2*>(C + (size_t)r * HIDN + c) = v0;
            *reinterpret_cast<float2*>(C + (size_t)(r + 8) * HIDN + c) = v1;
        }
    }
}

// ---------------------------------------------------------------------------
// IndRNN scan, software-pipelined prefetch (16 deep). fp32 output variant.
// ---------------------------------------------------------------------------
__global__ __launch_bounds__(256)
void indrnn_scan_f32(const float* __restrict__ lin, const float* __restrict__ rec,
                     float* __restrict__ y, float* __restrict__ hid_out, int off)
{
    const int idx = blockIdx.x * 256 + threadIdx.x;
    const int h = idx & (HIDN - 1);
    const int b = idx >> 10;
    const float r = rec[h];
    const float* p = lin + idx;
    float* q = y + idx;

    float cur[16], nxt[16];
#pragma unroll
    for (int u = 0; u < 16; u++) cur[u] = p[(size_t)u * BH];

    float hv = 0.0f;
    for (int s0 = 0; s0 < SEQ; s0 += 16) {
        if (s0 + 16 < SEQ) {
#pragma unroll
            for (int u = 0; u < 16; u++) nxt[u] = p[(size_t)(s0 + 16 + u) * BH];
        }
#pragma unroll
        for (int u = 0; u < 16; u++) {
            hv = fmaxf(fmaf(r, hv, cur[u]), 0.0f);
            q[(size_t)(s0 + u) * BH] = hv;
        }
#pragma unroll
        for (int u = 0; u < 16; u++) cur[u] = nxt[u];
    }
    hid_out[(size_t)b * (2 * HIDN) + off + h] = hv;
}

// Variant writing bf16 hi/lo splits directly (feeds the next layer's GEMM).
__global__ __launch_bounds__(256)
void indrnn_scan_split(const float* __restrict__ lin, const float* __restrict__ rec,
                       __nv_bfloat16* __restrict__ yhi, __nv_bfloat16* __restrict__ ylo,
                       float* __restrict__ hid_out, int off)
{
    const int idx = blockIdx.x * 256 + threadIdx.x;
    const int h = idx & (HIDN - 1);
    const int b = idx >> 10;
    const float r = rec[h];
    const float* p = lin + idx;

    float cur[16], nxt[16];
#pragma unroll
    for (int u = 0; u < 16; u++) cur[u] = p[(size_t)u * BH];

    float hv = 0.0f;
    for (int s0 = 0; s0 < SEQ; s0 += 16) {
        if (s0 + 16 < SEQ) {
#pragma unroll
            for (int u = 0; u < 16; u++) nxt[u] = p[(size_t)(s0 + 16 + u) * BH];
        }
#pragma unroll
        for (int u = 0; u < 16; u++) {
            hv = fmaxf(fmaf(r, hv, cur[u]), 0.0f);
            __nv_bfloat16 hb = __float2bfloat16(hv);
            yhi[(size_t)(s0 + u) * BH + idx] = hb;
            ylo[(size_t)(s0 + u) * BH + idx] = __float2bfloat16(hv - __bfloat162float(hb));
        }
#pragma unroll
        for (int u = 0; u < 16; u++) cur[u] = nxt[u];
    }
    hid_out[(size_t)b * (2 * HIDN) + off + h] = hv;
}

// ---------------------------------------------------------------------------
// kernel_launch
// Inputs: x (S,B,IN), w0 (H,IN), b0 (H), w1 (H,H), b1 (H), rec (2,H)
// Output: y1 (S,B,H) then hiddens (B, 2H)
// ---------------------------------------------------------------------------
extern "C" void kernel_launch(void* const* d_in, const int* in_sizes, int n_in,
                              void* d_out, int out_size)
{
    const float* x   = (const float*)d_in[0];
    const float* w0  = (const float*)d_in[1];
    const float* b0  = (const float*)d_in[2];
    const float* w1  = (const float*)d_in[3];
    const float* b1  = (const float*)d_in[4];
    const float* rec = (const float*)d_in[5];

    float* out     = (float*)d_out;
    float* y1_out  = out;
    float* hid_out = out + (size_t)MTOT * HIDN;

    __nv_bfloat16 *Ahi, *Alo, *Whi, *Wlo;
    float* lin;
    cudaGetSymbolAddress((void**)&Ahi, g_Ahi);
    cudaGetSymbolAddress((void**)&Alo, g_Alo);
    cudaGetSymbolAddress((void**)&Whi, g_Whi);
    cudaGetSymbolAddress((void**)&Wlo, g_Wlo);
    cudaGetSymbolAddress((void**)&lin, g_lin);

    cudaFuncSetAttribute(gemm_mma_split, cudaFuncAttributeMaxDynamicSharedMemorySize, GEMM_SMEM);

    const int nX4 = MTOT * KDIM / 4;
    const int nW4 = HIDN * KDIM / 4;

    dim3 ggrid(HIDN / 128, MTOT / 128);  // (8, 64)
    dim3 sgrid(BH / 256);                // 128

    // Layer 0
    split_fp32_bf16<<<(nX4 + 255) / 256, 256>>>(x, Ahi, Alo, nX4);
    split_fp32_bf16<<<(nW4 + 255) / 256, 256>>>(w0, Whi, Wlo, nW4);
    gemm_mma_split<<<ggrid, 256, GEMM_SMEM>>>(Ahi, Alo, Whi, Wlo, b0, lin);
    indrnn_scan_split<<<sgrid, 256>>>(lin, rec, Ahi, Alo, hid_out, 0);

    // Layer 1
    split_fp32_bf16<<<(nW4 + 255) / 256, 256>>>(w1, Whi, Wlo, nW4);
    gemm_mma_split<<<ggrid, 256, GEMM_SMEM>>>(Ahi, Alo, Whi, Wlo, b1, lin);
    indrnn_scan_f32<<<sgrid, 256>>>(lin, rec + HIDN, y1_out, hid_out, HIDN);
}

// round 5
// speedup vs baseline: 3.3422x; 1.2410x over previous
#include <cuda_runtime.h>
#include <cuda_bf16.h>
#include <cstdint>

// Problem dims
#define SEQ   256
#define BATCH 32
#define HIDN  1024
#define KDIM  1024
#define MTOT  (SEQ * BATCH)        // 8192
#define BH    (BATCH * HIDN)       // 32768

// ---------------------------------------------------------------------------
// Device-global scratch (no allocation allowed)
// ---------------------------------------------------------------------------
__device__ __align__(16) __nv_bfloat16 g_Ahi[MTOT * KDIM];   // 16 MB
__device__ __align__(16) __nv_bfloat16 g_Alo[MTOT * KDIM];   // 16 MB
__device__ __align__(16) __nv_bfloat16 g_Whi[HIDN * KDIM];   // 2 MB
__device__ __align__(16) __nv_bfloat16 g_Wlo[HIDN * KDIM];   // 2 MB
__device__ __align__(16) float         g_lin[MTOT * HIDN];   // 32 MB

// ---------------------------------------------------------------------------
// PTX helpers (base sm_103 features only: cp.async, ldmatrix, mma.sync)
// ---------------------------------------------------------------------------
__device__ __forceinline__ uint32_t smem_to_u32(const void* p) {
    uint32_t a;
    asm("{ .reg .u64 t; cvta.to.shared.u64 t, %1; cvt.u32.u64 %0, t; }" : "=r"(a) : "l"(p));
    return a;
}

__device__ __forceinline__ void cp16(uint32_t s, const void* g) {
    asm volatile("cp.async.cg.shared.global [%0], [%1], 16;" :: "r"(s), "l"(g));
}
#define CP_COMMIT() asm volatile("cp.async.commit_group;" ::: "memory")
#define CP_WAIT(n)  asm volatile("cp.async.wait_group %0;" :: "n"(n) : "memory")

__device__ __forceinline__ void ldsm4(uint32_t& r0, uint32_t& r1, uint32_t& r2,
                                      uint32_t& r3, uint32_t addr) {
    asm volatile("ldmatrix.sync.aligned.m8n8.x4.shared.b16 {%0,%1,%2,%3}, [%4];"
        : "=r"(r0), "=r"(r1), "=r"(r2), "=r"(r3) : "r"(addr));
}

__device__ __forceinline__ void mma16816(float* c, const uint32_t* a, const uint32_t* b) {
    asm volatile(
        "mma.sync.aligned.m16n8k16.row.col.f32.bf16.bf16.f32 "
        "{%0,%1,%2,%3}, {%4,%5,%6,%7}, {%8,%9}, {%0,%1,%2,%3};"
        : "+f"(c[0]), "+f"(c[1]), "+f"(c[2]), "+f"(c[3])
        : "r"(a[0]), "r"(a[1]), "r"(a[2]), "r"(a[3]), "r"(b[0]), "r"(b[1]));
}

// XOR swizzle for 64B rows (4x 16B chunks): conflict-free for ldmatrix phases
// and cp.async store phases. period = 8 rows.
__device__ __forceinline__ uint32_t sw_off(int row, int ch) {
    return (uint32_t)((row << 6) + ((ch ^ ((row >> 1) & 3)) << 4));
}

// ---------------------------------------------------------------------------
// Split fp32 -> bf16 hi + lo (vectorized by 4)
// ---------------------------------------------------------------------------
__global__ __launch_bounds__(256)
void split_fp32_bf16(const float* __restrict__ in,
                     __nv_bfloat16* __restrict__ hi,
                     __nv_bfloat16* __restrict__ lo, int n4)
{
    int i = blockIdx.x * blockDim.x + threadIdx.x;
    if (i >= n4) return;
    float4 v = reinterpret_cast<const float4*>(in)[i];
    float f[4] = {v.x, v.y, v.z, v.w};
    union { __nv_bfloat16 b[4]; uint2 u; } H, L;
#pragma unroll
    for (int j = 0; j < 4; j++) {
        __nv_bfloat16 h = __float2bfloat16(f[j]);
        H.b[j] = h;
        L.b[j] = __float2bfloat16(f[j] - __bfloat162float(h));
    }
    reinterpret_cast<uint2*>(hi)[i] = H.u;
    reinterpret_cast<uint2*>(lo)[i] = L.u;
}

// ---------------------------------------------------------------------------
// mma.sync bf16-split GEMM: C[m,n] = sum_k A[m,k]*W[n,k] + bias[n]
// acc += Ahi*Whi + Ahi*Wlo + Alo*Whi (fp32 regs).
// CTA tile 128x128, K-stage 32, 3-stage cp.async pipeline, XOR-swizzled smem.
// 8 warps: warp tile 64(m) x 32(n).
// ---------------------------------------------------------------------------
#define STAGES      3
#define BKC         32
#define NKS         (KDIM / BKC)              // 32
#define TILEB       (128 * 64)                // 8192 bytes per tile
#define STAGEB      (4 * TILEB)               // 32768
#define GEMM_SMEM   (STAGES * STAGEB)         // 98304

__device__ __forceinline__ void load_stage(uint32_t sb, int buf, int s,
                                           const __nv_bfloat16* __restrict__ Ahi,
                                           const __nv_bfloat16* __restrict__ Alo,
                                           const __nv_bfloat16* __restrict__ Whi,
                                           const __nv_bfloat16* __restrict__ Wlo,
                                           int m0, int n0, int tid)
{
    const int kc = s * BKC;
    const uint32_t base = sb + buf * STAGEB;
#pragma unroll
    for (int it = 0; it < 2; it++) {
        int t = tid + it * 256;          // 0..511 -> 128 rows x 4 chunks
        int row = t >> 2;
        int ch = t & 3;
        uint32_t soff = sw_off(row, ch);
        size_t goffA = (size_t)(m0 + row) * KDIM + kc + ch * 8;
        size_t goffW = (size_t)(n0 + row) * KDIM + kc + ch * 8;
        cp16(base + 0 * TILEB + soff, Ahi + goffA);
        cp16(base + 1 * TILEB + soff, Alo + goffA);
        cp16(base + 2 * TILEB + soff, Whi + goffW);
        cp16(base + 3 * TILEB + soff, Wlo + goffW);
    }
}

__global__ __launch_bounds__(256, 2)
void gemm_mma_split(const __nv_bfloat16* __restrict__ Ahi,
                    const __nv_bfloat16* __restrict__ Alo,
                    const __nv_bfloat16* __restrict__ Whi,
                    const __nv_bfloat16* __restrict__ Wlo,
                    const float* __restrict__ bias,
                    float* __restrict__ C)
{
    extern __shared__ __align__(16) char smem[];
    const uint32_t sb = smem_to_u32(smem);
    const int tid = threadIdx.x;
    const int wid = tid >> 5;
    const int lane = tid & 31;
    const int m0 = blockIdx.y * 128;
    const int n0 = blockIdx.x * 128;
    const int wm = (wid >> 2) * 64;      // warp row offset in tile
    const int wn = (wid & 3) * 32;       // warp col offset in tile

    float acc[4][4][4];
#pragma unroll
    for (int i = 0; i < 4; i++)
#pragma unroll
        for (int j = 0; j < 4; j++)
#pragma unroll
            for (int r = 0; r < 4; r++) acc[i][j][r] = 0.0f;

    // ldmatrix lane addressing (fixed per thread)
    const int a_row = lane & 15;                        // + wm + mi*16
    const int a_ch  = lane >> 4;                        // 0/1 within k16
    const int b_row = (lane & 7) + ((lane >> 4) << 3);  // + wn + half*16
    const int b_ch  = (lane >> 3) & 1;

    // Prologue: prefetch stages 0 and 1
    load_stage(sb, 0, 0, Ahi, Alo, Whi, Wlo, m0, n0, tid);
    CP_COMMIT();
    load_stage(sb, 1, 1, Ahi, Alo, Whi, Wlo, m0, n0, tid);
    CP_COMMIT();

    int buf = 0;
    for (int s = 0; s < NKS; s++) {
        CP_WAIT(1);            // stage s resident
        __syncthreads();       // all warps done with buf (s-1)%3 -> safe to refill

        if (s + 2 < NKS) {
            int nbuf = buf + 2; if (nbuf >= STAGES) nbuf -= STAGES;
            load_stage(sb, nbuf, s + 2, Ahi, Alo, Whi, Wlo, m0, n0, tid);
        }
        CP_COMMIT();           // commit (possibly empty) group to keep count in sync

        const uint32_t st = sb + buf * STAGEB;
#pragma unroll
        for (int kk = 0; kk < 2; kk++) {
            uint32_t bhi[4][2], blo[4][2];
#pragma unroll
            for (int half = 0; half < 2; half++) {
                int br = wn + b_row + half * 16;
                int bc = kk * 2 + b_ch;
                uint32_t boff = sw_off(br, bc);
                ldsm4(bhi[half * 2][0], bhi[half * 2][1],
                      bhi[half * 2 + 1][0], bhi[half * 2 + 1][1],
                      st + 2 * TILEB + boff);
                ldsm4(blo[half * 2][0], blo[half * 2][1],
                      blo[half * 2 + 1][0], blo[half * 2 + 1][1],
                      st + 3 * TILEB + boff);
            }
#pragma unroll
            for (int mi = 0; mi < 4; mi++) {
                int ar = wm + mi * 16 + a_row;
                int ac = kk * 2 + a_ch;
                uint32_t aoff = sw_off(ar, ac);
                uint32_t ahi[4], alo[4];
                ldsm4(ahi[0], ahi[1], ahi[2], ahi[3], st + 0 * TILEB + aoff);
                ldsm4(alo[0], alo[1], alo[2], alo[3], st + 1 * TILEB + aoff);
#pragma unroll
                for (int ni = 0; ni < 4; ni++) {
                    mma16816(acc[mi][ni], ahi, bhi[ni]);
                    mma16816(acc[mi][ni], ahi, blo[ni]);
                    mma16816(acc[mi][ni], alo, bhi[ni]);
                }
            }
        }
        __syncthreads();
        buf++; if (buf >= STAGES) buf -= STAGES;
    }

    // Epilogue: add bias, store fp32
    const int er = lane >> 2;
    const int ec = (lane & 3) * 2;
#pragma unroll
    for (int mi = 0; mi < 4; mi++) {
        const int r = m0 + wm + mi * 16 + er;
#pragma unroll
        for (int ni = 0; ni < 4; ni++) {
            const int c = n0 + wn + ni * 8 + ec;
            const float b0 = __ldg(bias + c);
            const float b1 = __ldg(bias + c + 1);
            float2 v0 = {acc[mi][ni][0] + b0, acc[mi][ni][1] + b1};
            float2 v1 = {acc[mi][ni][2] + b0, acc[mi][ni][3] + b1};
            *reinterpret_cast<float2*>(C + (size_t)r * HIDN + c) = v0;
            *reinterpret_cast<float2*>(C + (size_t)(r + 8) * HIDN + c) = v1;
        }
    }
}

// ---------------------------------------------------------------------------
// IndRNN scan, software-pipelined prefetch (32 deep), 128-thread blocks.
// ---------------------------------------------------------------------------
__global__ __launch_bounds__(128)
void indrnn_scan_f32(const float* __restrict__ lin, const float* __restrict__ rec,
                     float* __restrict__ y, float* __restrict__ hid_out, int off)
{
    const int idx = blockIdx.x * 128 + threadIdx.x;
    const int h = idx & (HIDN - 1);
    const int b = idx >> 10;
    const float r = rec[h];
    const float* p = lin + idx;
    float* q = y + idx;

    float cur[32], nxt[32];
#pragma unroll
    for (int u = 0; u < 32; u++) cur[u] = p[(size_t)u * BH];

    float hv = 0.0f;
    for (int s0 = 0; s0 < SEQ; s0 += 32) {
        if (s0 + 32 < SEQ) {
#pragma unroll
            for (int u = 0; u < 32; u++) nxt[u] = p[(size_t)(s0 + 32 + u) * BH];
        }
#pragma unroll
        for (int u = 0; u < 32; u++) {
            hv = fmaxf(fmaf(r, hv, cur[u]), 0.0f);
            q[(size_t)(s0 + u) * BH] = hv;
        }
#pragma unroll
        for (int u = 0; u < 32; u++) cur[u] = nxt[u];
    }
    hid_out[(size_t)b * (2 * HIDN) + off + h] = hv;
}

// Variant writing bf16 hi/lo splits directly (feeds the next layer's GEMM).
__global__ __launch_bounds__(128)
void indrnn_scan_split(const float* __restrict__ lin, const float* __restrict__ rec,
                       __nv_bfloat16* __restrict__ yhi, __nv_bfloat16* __restrict__ ylo,
                       float* __restrict__ hid_out, int off)
{
    const int idx = blockIdx.x * 128 + threadIdx.x;
    const int h = idx & (HIDN - 1);
    const int b = idx >> 10;
    const float r = rec[h];
    const float* p = lin + idx;

    float cur[32], nxt[32];
#pragma unroll
    for (int u = 0; u < 32; u++) cur[u] = p[(size_t)u * BH];

    float hv = 0.0f;
    for (int s0 = 0; s0 < SEQ; s0 += 32) {
        if (s0 + 32 < SEQ) {
#pragma unroll
            for (int u = 0; u < 32; u++) nxt[u] = p[(size_t)(s0 + 32 + u) * BH];
        }
#pragma unroll
        for (int u = 0; u < 32; u++) {
            hv = fmaxf(fmaf(r, hv, cur[u]), 0.0f);
            __nv_bfloat16 hb = __float2bfloat16(hv);
            yhi[(size_t)(s0 + u) * BH + idx] = hb;
            ylo[(size_t)(s0 + u) * BH + idx] = __float2bfloat16(hv - __bfloat162float(hb));
        }
#pragma unroll
        for (int u = 0; u < 32; u++) cur[u] = nxt[u];
    }
    hid_out[(size_t)b * (2 * HIDN) + off + h] = hv;
}

// ---------------------------------------------------------------------------
// kernel_launch
// Inputs: x (S,B,IN), w0 (H,IN), b0 (H), w1 (H,H), b1 (H), rec (2,H)
// Output: y1 (S,B,H) then hiddens (B, 2H)
// ---------------------------------------------------------------------------
extern "C" void kernel_launch(void* const* d_in, const int* in_sizes, int n_in,
                              void* d_out, int out_size)
{
    const float* x   = (const float*)d_in[0];
    const float* w0  = (const float*)d_in[1];
    const float* b0  = (const float*)d_in[2];
    const float* w1  = (const float*)d_in[3];
    const float* b1  = (const float*)d_in[4];
    const float* rec = (const float*)d_in[5];

    float* out     = (float*)d_out;
    float* y1_out  = out;
    float* hid_out = out + (size_t)MTOT * HIDN;

    __nv_bfloat16 *Ahi, *Alo, *Whi, *Wlo;
    float* lin;
    cudaGetSymbolAddress((void**)&Ahi, g_Ahi);
    cudaGetSymbolAddress((void**)&Alo, g_Alo);
    cudaGetSymbolAddress((void**)&Whi, g_Whi);
    cudaGetSymbolAddress((void**)&Wlo, g_Wlo);
    cudaGetSymbolAddress((void**)&lin, g_lin);

    cudaFuncSetAttribute(gemm_mma_split, cudaFuncAttributeMaxDynamicSharedMemorySize, GEMM_SMEM);

    const int nX4 = MTOT * KDIM / 4;
    const int nW4 = HIDN * KDIM / 4;

    dim3 ggrid(HIDN / 128, MTOT / 128);  // (8, 64)
    dim3 sgrid(BH / 128);                // 256

    // Layer 0
    split_fp32_bf16<<<(nX4 + 255) / 256, 256>>>(x, Ahi, Alo, nX4);
    split_fp32_bf16<<<(nW4 + 255) / 256, 256>>>(w0, Whi, Wlo, nW4);
    gemm_mma_split<<<ggrid, 256, GEMM_SMEM>>>(Ahi, Alo, Whi, Wlo, b0, lin);
    indrnn_scan_split<<<sgrid, 128>>>(lin, rec, Ahi, Alo, hid_out, 0);

    // Layer 1
    split_fp32_bf16<<<(nW4 + 255) / 256, 256>>>(w1, Whi, Wlo, nW4);
    gemm_mma_split<<<ggrid, 256, GEMM_SMEM>>>(Ahi, Alo, Whi, Wlo, b1, lin);
    indrnn_scan_f32<<<sgrid, 128>>>(lin, rec + HIDN, y1_out, hid_out, HIDN);
}

// round 8
// speedup vs baseline: 3.3467x; 1.0014x over previous
#include <cuda_runtime.h>
#include <cuda_bf16.h>
#include <cstdint>

// Problem dims
#define SEQ   256
#define BATCH 32
#define HIDN  1024
#define KDIM  1024
#define MTOT  (SEQ * BATCH)        // 8192
#define BH    (BATCH * HIDN)       // 32768

// ---------------------------------------------------------------------------
// Device-global scratch (no allocation allowed)
// ---------------------------------------------------------------------------
__device__ __align__(16) __nv_bfloat16 g_Ahi[MTOT * KDIM];   // 16 MB
__device__ __align__(16) __nv_bfloat16 g_Alo[MTOT * KDIM];   // 16 MB
__device__ __align__(16) __nv_bfloat16 g_Whi[HIDN * KDIM];   // 2 MB
__device__ __align__(16) __nv_bfloat16 g_Wlo[HIDN * KDIM];   // 2 MB
__device__ __align__(16) float         g_lin[MTOT * HIDN];   // 32 MB

// ---------------------------------------------------------------------------
// PTX helpers (base sm_103 features only: cp.async, ldmatrix, mma.sync)
// ---------------------------------------------------------------------------
__device__ __forceinline__ uint32_t smem_to_u32(const void* p) {
    uint32_t a;
    asm("{ .reg .u64 t; cvta.to.shared.u64 t, %1; cvt.u32.u64 %0, t; }" : "=r"(a) : "l"(p));
    return a;
}

__device__ __forceinline__ void cp16(uint32_t s, const void* g) {
    asm volatile("cp.async.cg.shared.global [%0], [%1], 16;" :: "r"(s), "l"(g));
}
#define CP_COMMIT() asm volatile("cp.async.commit_group;" ::: "memory")
#define CP_WAIT(n)  asm volatile("cp.async.wait_group %0;" :: "n"(n) : "memory")

__device__ __forceinline__ void ldsm4(uint32_t& r0, uint32_t& r1, uint32_t& r2,
                                      uint32_t& r3, uint32_t addr) {
    asm volatile("ldmatrix.sync.aligned.m8n8.x4.shared.b16 {%0,%1,%2,%3}, [%4];"
        : "=r"(r0), "=r"(r1), "=r"(r2), "=r"(r3) : "r"(addr));
}

__device__ __forceinline__ void mma16816(float* c, const uint32_t* a, const uint32_t* b) {
    asm volatile(
        "mma.sync.aligned.m16n8k16.row.col.f32.bf16.bf16.f32 "
        "{%0,%1,%2,%3}, {%4,%5,%6,%7}, {%8,%9}, {%0,%1,%2,%3};"
        : "+f"(c[0]), "+f"(c[1]), "+f"(c[2]), "+f"(c[3])
        : "r"(a[0]), "r"(a[1]), "r"(a[2]), "r"(a[3]), "r"(b[0]), "r"(b[1]));
}

// XOR swizzle for 64B rows (4x 16B chunks): conflict-free for ldmatrix phases
// and cp.async store phases. period = 8 rows.
__device__ __forceinline__ uint32_t sw_off(int row, int ch) {
    return (uint32_t)((row << 6) + ((ch ^ ((row >> 1) & 3)) << 4));
}

// ---------------------------------------------------------------------------
// Split fp32 -> bf16 hi + lo (vectorized by 4)
// ---------------------------------------------------------------------------
__global__ __launch_bounds__(256)
void split_fp32_bf16(const float* __restrict__ in,
                     __nv_bfloat16* __restrict__ hi,
                     __nv_bfloat16* __restrict__ lo, int n4)
{
    int i = blockIdx.x * blockDim.x + threadIdx.x;
    if (i >= n4) return;
    float4 v = reinterpret_cast<const float4*>(in)[i];
    float f[4] = {v.x, v.y, v.z, v.w};
    union { __nv_bfloat16 b[4]; uint2 u; } H, L;
#pragma unroll
    for (int j = 0; j < 4; j++) {
        __nv_bfloat16 h = __float2bfloat16(f[j]);
        H.b[j] = h;
        L.b[j] = __float2bfloat16(f[j] - __bfloat162float(h));
    }
    reinterpret_cast<uint2*>(hi)[i] = H.u;
    reinterpret_cast<uint2*>(lo)[i] = L.u;
}

// ---------------------------------------------------------------------------
// mma.sync bf16-split GEMM: C[m,n] = sum_k A[m,k]*W[n,k] + bias[n]
// acc += Ahi*Whi + Ahi*Wlo + Alo*Whi (fp32 regs), pass-major for ILP.
// CTA tile 128x128, K-stage 32, 3-stage cp.async pipeline, XOR-swizzled smem.
// 8 warps: warp tile 64(m) x 32(n).
// ---------------------------------------------------------------------------
#define STAGES      3
#define BKC         32
#define NKS         (KDIM / BKC)              // 32
#define TILEB       (128 * 64)                // 8192 bytes per tile
#define STAGEB      (4 * TILEB)               // 32768
#define GEMM_SMEM   (STAGES * STAGEB)         // 98304

__device__ __forceinline__ void load_stage(uint32_t sb, int buf, int s,
                                           const __nv_bfloat16* __restrict__ Ahi,
                                           const __nv_bfloat16* __restrict__ Alo,
                                           const __nv_bfloat16* __restrict__ Whi,
                                           const __nv_bfloat16* __restrict__ Wlo,
                                           int m0, int n0, int tid)
{
    const int kc = s * BKC;
    const uint32_t base = sb + buf * STAGEB;
#pragma unroll
    for (int it = 0; it < 2; it++) {
        int t = tid + it * 256;          // 0..511 -> 128 rows x 4 chunks
        int row = t >> 2;
        int ch = t & 3;
        uint32_t soff = sw_off(row, ch);
        size_t goffA = (size_t)(m0 + row) * KDIM + kc + ch * 8;
        size_t goffW = (size_t)(n0 + row) * KDIM + kc + ch * 8;
        cp16(base + 0 * TILEB + soff, Ahi + goffA);
        cp16(base + 1 * TILEB + soff, Alo + goffA);
        cp16(base + 2 * TILEB + soff, Whi + goffW);
        cp16(base + 3 * TILEB + soff, Wlo + goffW);
    }
}

__global__ __launch_bounds__(256, 2)
void gemm_mma_split(const __nv_bfloat16* __restrict__ Ahi,
                    const __nv_bfloat16* __restrict__ Alo,
                    const __nv_bfloat16* __restrict__ Whi,
                    const __nv_bfloat16* __restrict__ Wlo,
                    const float* __restrict__ bias,
                    float* __restrict__ C)
{
    extern __shared__ __align__(16) char smem[];
    const uint32_t sb = smem_to_u32(smem);
    const int tid = threadIdx.x;
    const int wid = tid >> 5;
    const int lane = tid & 31;
    const int m0 = blockIdx.y * 128;
    const int n0 = blockIdx.x * 128;
    const int wm = (wid >> 2) * 64;      // warp row offset in tile
    const int wn = (wid & 3) * 32;       // warp col offset in tile

    float acc[4][4][4];
#pragma unroll
    for (int i = 0; i < 4; i++)
#pragma unroll
        for (int j = 0; j < 4; j++)
#pragma unroll
            for (int r = 0; r < 4; r++) acc[i][j][r] = 0.0f;

    // ldmatrix lane addressing (fixed per thread)
    const int a_row = lane & 15;                        // + wm + mi*16
    const int a_ch  = lane >> 4;                        // 0/1 within k16
    const int b_row = (lane & 7) + ((lane >> 4) << 3);  // + wn + half*16
    const int b_ch  = (lane >> 3) & 1;

    // Prologue: prefetch stages 0 and 1
    load_stage(sb, 0, 0, Ahi, Alo, Whi, Wlo, m0, n0, tid);
    CP_COMMIT();
    load_stage(sb, 1, 1, Ahi, Alo, Whi, Wlo, m0, n0, tid);
    CP_COMMIT();

    int buf = 0;
    for (int s = 0; s < NKS; s++) {
        CP_WAIT(1);            // stage s resident
        __syncthreads();       // all warps done with the buffer we refill below

        if (s + 2 < NKS) {
            int nbuf = buf + 2; if (nbuf >= STAGES) nbuf -= STAGES;
            load_stage(sb, nbuf, s + 2, Ahi, Alo, Whi, Wlo, m0, n0, tid);
        }
        CP_COMMIT();           // commit (possibly empty) group to keep count in sync

        const uint32_t st = sb + buf * STAGEB;
#pragma unroll
        for (int kk = 0; kk < 2; kk++) {
            // --- load Ahi + Bhi fragments ---
            uint32_t ahi[4][4], bhi[4][2];
#pragma unroll
            for (int mi = 0; mi < 4; mi++) {
                uint32_t aoff = sw_off(wm + mi * 16 + a_row, kk * 2 + a_ch);
                ldsm4(ahi[mi][0], ahi[mi][1], ahi[mi][2], ahi[mi][3],
                      st + 0 * TILEB + aoff);
            }
#pragma unroll
            for (int half = 0; half < 2; half++) {
                uint32_t boff = sw_off(wn + b_row + half * 16, kk * 2 + b_ch);
                ldsm4(bhi[half * 2][0], bhi[half * 2][1],
                      bhi[half * 2 + 1][0], bhi[half * 2 + 1][1],
                      st + 2 * TILEB + boff);
            }
            // --- pass 1: hi * hi (16 independent MMAs) ---
#pragma unroll
            for (int mi = 0; mi < 4; mi++)
#pragma unroll
                for (int ni = 0; ni < 4; ni++)
                    mma16816(acc[mi][ni], ahi[mi], bhi[ni]);

            // --- load Blo, pass 2: hi * lo ---
            uint32_t blo[4][2];
#pragma unroll
            for (int half = 0; half < 2; half++) {
                uint32_t boff = sw_off(wn + b_row + half * 16, kk * 2 + b_ch);
                ldsm4(blo[half * 2][0], blo[half * 2][1],
                      blo[half * 2 + 1][0], blo[half * 2 + 1][1],
                      st + 3 * TILEB + boff);
            }
#pragma unroll
            for (int mi = 0; mi < 4; mi++)
#pragma unroll
                for (int ni = 0; ni < 4; ni++)
                    mma16816(acc[mi][ni], ahi[mi], blo[ni]);

            // --- load Alo, pass 3: lo * hi ---
            uint32_t alo[4][4];
#pragma unroll
            for (int mi = 0; mi < 4; mi++) {
                uint32_t aoff = sw_off(wm + mi * 16 + a_row, kk * 2 + a_ch);
                ldsm4(alo[mi][0], alo[mi][1], alo[mi][2], alo[mi][3],
                      st + 1 * TILEB + aoff);
            }
#pragma unroll
            for (int mi = 0; mi < 4; mi++)
#pragma unroll
                for (int ni = 0; ni < 4; ni++)
                    mma16816(acc[mi][ni], alo[mi], bhi[ni]);
        }
        buf++; if (buf >= STAGES) buf -= STAGES;
    }

    // Epilogue: add bias, store fp32
    const int er = lane >> 2;
    const int ec = (lane & 3) * 2;
#pragma unroll
    for (int mi = 0; mi < 4; mi++) {
        const int r = m0 + wm + mi * 16 + er;
#pragma unroll
        for (int ni = 0; ni < 4; ni++) {
            const int c = n0 + wn + ni * 8 + ec;
            const float b0 = __ldg(bias + c);
            const float b1 = __ldg(bias + c + 1);
            float2 v0 = {acc[mi][ni][0] + b0, acc[mi][ni][1] + b1};
            float2 v1 = {acc[mi][ni][2] + b0, acc[mi][ni][3] + b1};
            *reinterpret_cast<float2*>(C + (size_t)r * HIDN + c) = v0;
            *reinterpret_cast<float2*>(C + (size_t)(r + 8) * HIDN + c) = v1;
        }
    }
}

// ---------------------------------------------------------------------------
// IndRNN scan, software-pipelined prefetch (32 deep), 128-thread blocks.
// ---------------------------------------------------------------------------
__global__ __launch_bounds__(128)
void indrnn_scan_f32(const float* __restrict__ lin, const float* __restrict__ rec,
                     float* __restrict__ y, float* __restrict__ hid_out, int off)
{
    const int idx = blockIdx.x * 128 + threadIdx.x;
    const int h = idx & (HIDN - 1);
    const int b = idx >> 10;
    const float r = rec[h];
    const float* p = lin + idx;
    float* q = y + idx;

    float cur[32], nxt[32];
#pragma unroll
    for (int u = 0; u < 32; u++) cur[u] = __ldcs(p + (size_t)u * BH);

    float hv = 0.0f;
    for (int s0 = 0; s0 < SEQ; s0 += 32) {
        if (s0 + 32 < SEQ) {
#pragma unroll
            for (int u = 0; u < 32; u++) nxt[u] = __ldcs(p + (size_t)(s0 + 32 + u) * BH);
        }
#pragma unroll
        for (int u = 0; u < 32; u++) {
            hv = fmaxf(fmaf(r, hv, cur[u]), 0.0f);
            q[(size_t)(s0 + u) * BH] = hv;
        }
#pragma unroll
        for (int u = 0; u < 32; u++) cur[u] = nxt[u];
    }
    hid_out[(size_t)b * (2 * HIDN) + off + h] = hv;
}

// Variant writing bf16 hi/lo splits directly (feeds the next layer's GEMM).
__global__ __launch_bounds__(128)
void indrnn_scan_split(const float* __restrict__ lin, const float* __restrict__ rec,
                       __nv_bfloat16* __restrict__ yhi, __nv_bfloat16* __restrict__ ylo,
                       float* __restrict__ hid_out, int off)
{
    const int idx = blockIdx.x * 128 + threadIdx.x;
    const int h = idx & (HIDN - 1);
    const int b = idx >> 10;
    const float r = rec[h];
    const float* p = lin + idx;

    float cur[32], nxt[32];
#pragma unroll
    for (int u = 0; u < 32; u++) cur[u] = __ldcs(p + (size_t)u * BH);

    float hv = 0.0f;
    for (int s0 = 0; s0 < SEQ; s0 += 32) {
        if (s0 + 32 < SEQ) {
#pragma unroll
            for (int u = 0; u < 32; u++) nxt[u] = __ldcs(p + (size_t)(s0 + 32 + u) * BH);
        }
#pragma unroll
        for (int u = 0; u < 32; u++) {
            hv = fmaxf(fmaf(r, hv, cur[u]), 0.0f);
            __nv_bfloat16 hb = __float2bfloat16(hv);
            yhi[(size_t)(s0 + u) * BH + idx] = hb;
            ylo[(size_t)(s0 + u) * BH + idx] = __float2bfloat16(hv - __bfloat162float(hb));
        }
#pragma unroll
        for (int u = 0; u < 32; u++) cur[u] = nxt[u];
    }
    hid_out[(size_t)b * (2 * HIDN) + off + h] = hv;
}

// ---------------------------------------------------------------------------
// kernel_launch
// Inputs: x (S,B,IN), w0 (H,IN), b0 (H), w1 (H,H), b1 (H), rec (2,H)
// Output: y1 (S,B,H) then hiddens (B, 2H)
// ---------------------------------------------------------------------------
extern "C" void kernel_launch(void* const* d_in, const int* in_sizes, int n_in,
                              void* d_out, int out_size)
{
    const float* x   = (const float*)d_in[0];
    const float* w0  = (const float*)d_in[1];
    const float* b0  = (const float*)d_in[2];
    const float* w1  = (const float*)d_in[3];
    const float* b1  = (const float*)d_in[4];
    const float* rec = (const float*)d_in[5];

    float* out     = (float*)d_out;
    float* y1_out  = out;
    float* hid_out = out + (size_t)MTOT * HIDN;

    __nv_bfloat16 *Ahi, *Alo, *Whi, *Wlo;
    float* lin;
    cudaGetSymbolAddress((void**)&Ahi, g_Ahi);
    cudaGetSymbolAddress((void**)&Alo, g_Alo);
    cudaGetSymbolAddress((void**)&Whi, g_Whi);
    cudaGetSymbolAddress((void**)&Wlo, g_Wlo);
    cudaGetSymbolAddress((void**)&lin, g_lin);

    cudaFuncSetAttribute(gemm_mma_split, cudaFuncAttributeMaxDynamicSharedMemorySize, GEMM_SMEM);

    const int nX4 = MTOT * KDIM / 4;
    const int nW4 = HIDN * KDIM / 4;

    dim3 ggrid(HIDN / 128, MTOT / 128);  // (8, 64)
    dim3 sgrid(BH / 128);                // 256

    // Layer 0
    split_fp32_bf16<<<(nX4 + 255) / 256, 256>>>(x, Ahi, Alo, nX4);
    split_fp32_bf16<<<(nW4 + 255) / 256, 256>>>(w0, Whi, Wlo, nW4);
    gemm_mma_split<<<ggrid, 256, GEMM_SMEM>>>(Ahi, Alo, Whi, Wlo, b0, lin);
    indrnn_scan_split<<<sgrid, 128>>>(lin, rec, Ahi, Alo, hid_out, 0);

    // Layer 1
    split_fp32_bf16<<<(nW4 + 255) / 256, 256>>>(w1, Whi, Wlo, nW4);
    gemm_mma_split<<<ggrid, 256, GEMM_SMEM>>>(Ahi, Alo, Whi, Wlo, b1, lin);
    indrnn_scan_f32<<<sgrid, 128>>>(lin, rec + HIDN, y1_out, hid_out, HIDN);
}

// round 9
// speedup vs baseline: 7.3535x; 2.1972x over previous
#include <cuda_runtime.h>
#include <cuda_fp16.h>
#include <cstdint>

// Problem dims
#define SEQ   256
#define BATCH 32
#define HIDN  1024
#define KDIM  1024
#define MTOT  (SEQ * BATCH)        // 8192
#define BH    (BATCH * HIDN)       // 32768

// ---------------------------------------------------------------------------
// Device-global scratch (no allocation allowed)
// ---------------------------------------------------------------------------
__device__ __align__(16) __half g_Ah[MTOT * KDIM];   // 16 MB (x / y0 in fp16)
__device__ __align__(16) __half g_Wh[HIDN * KDIM];   // 2 MB
__device__ __align__(16) float  g_lin[MTOT * HIDN];  // 32 MB

// ---------------------------------------------------------------------------
// PTX helpers (base sm_103 features only: cp.async, ldmatrix, mma.sync)
// ---------------------------------------------------------------------------
__device__ __forceinline__ uint32_t smem_to_u32(const void* p) {
    uint32_t a;
    asm("{ .reg .u64 t; cvta.to.shared.u64 t, %1; cvt.u32.u64 %0, t; }" : "=r"(a) : "l"(p));
    return a;
}

__device__ __forceinline__ void cp16(uint32_t s, const void* g) {
    asm volatile("cp.async.cg.shared.global [%0], [%1], 16;" :: "r"(s), "l"(g));
}
#define CP_COMMIT() asm volatile("cp.async.commit_group;" ::: "memory")
#define CP_WAIT(n)  asm volatile("cp.async.wait_group %0;" :: "n"(n) : "memory")

__device__ __forceinline__ void ldsm4(uint32_t& r0, uint32_t& r1, uint32_t& r2,
                                      uint32_t& r3, uint32_t addr) {
    asm volatile("ldmatrix.sync.aligned.m8n8.x4.shared.b16 {%0,%1,%2,%3}, [%4];"
        : "=r"(r0), "=r"(r1), "=r"(r2), "=r"(r3) : "r"(addr));
}

__device__ __forceinline__ void mma16816h(float* c, const uint32_t* a, const uint32_t* b) {
    asm volatile(
        "mma.sync.aligned.m16n8k16.row.col.f32.f16.f16.f32 "
        "{%0,%1,%2,%3}, {%4,%5,%6,%7}, {%8,%9}, {%0,%1,%2,%3};"
        : "+f"(c[0]), "+f"(c[1]), "+f"(c[2]), "+f"(c[3])
        : "r"(a[0]), "r"(a[1]), "r"(a[2]), "r"(a[3]), "r"(b[0]), "r"(b[1]));
}

// XOR swizzle for 64B rows (4x 16B chunks): conflict-free for ldmatrix phases
// and cp.async store phases. period = 8 rows.
__device__ __forceinline__ uint32_t sw_off(int row, int ch) {
    return (uint32_t)((row << 6) + ((ch ^ ((row >> 1) & 3)) << 4));
}

// ---------------------------------------------------------------------------
// Convert fp32 -> fp16 (vectorized by 4)
// ---------------------------------------------------------------------------
__global__ __launch_bounds__(256)
void cvt_fp32_fp16(const float* __restrict__ in, __half* __restrict__ out, int n4)
{
    int i = blockIdx.x * blockDim.x + threadIdx.x;
    if (i >= n4) return;
    float4 v = reinterpret_cast<const float4*>(in)[i];
    union { __half h[4]; uint2 u; } H;
    H.h[0] = __float2half_rn(v.x);
    H.h[1] = __float2half_rn(v.y);
    H.h[2] = __float2half_rn(v.z);
    H.h[3] = __float2half_rn(v.w);
    reinterpret_cast<uint2*>(out)[i] = H.u;
}

// ---------------------------------------------------------------------------
// Single-pass fp16 mma.sync GEMM: C[m,n] = sum_k A[m,k]*W[n,k] + bias[n]
// fp32 register accumulators. CTA tile 128x128, K-stage 32, 4-stage cp.async
// pipeline, XOR-swizzled smem. 8 warps: warp tile 64(m) x 32(n).
// ---------------------------------------------------------------------------
#define STAGES      4
#define BKC         32
#define NKS         (KDIM / BKC)              // 32
#define TILEB       (128 * 64)                // 8192 bytes per tile
#define STAGEB      (2 * TILEB)               // 16384 (A + W)
#define GEMM_SMEM   (STAGES * STAGEB)         // 65536

__device__ __forceinline__ void load_stage(uint32_t sb, int buf, int s,
                                           const __half* __restrict__ A,
                                           const __half* __restrict__ W,
                                           int m0, int n0, int tid)
{
    const int kc = s * BKC;
    const uint32_t base = sb + buf * STAGEB;
#pragma unroll
    for (int it = 0; it < 2; it++) {
        int t = tid + it * 256;          // 0..511 -> 128 rows x 4 chunks
        int row = t >> 2;
        int ch = t & 3;
        uint32_t soff = sw_off(row, ch);
        cp16(base + 0 * TILEB + soff, A + (size_t)(m0 + row) * KDIM + kc + ch * 8);
        cp16(base + 1 * TILEB + soff, W + (size_t)(n0 + row) * KDIM + kc + ch * 8);
    }
}

__global__ __launch_bounds__(256, 2)
void gemm_fp16(const __half* __restrict__ A,
               const __half* __restrict__ W,
               const float* __restrict__ bias,
               float* __restrict__ C)
{
    extern __shared__ __align__(16) char smem[];
    const uint32_t sb = smem_to_u32(smem);
    const int tid = threadIdx.x;
    const int wid = tid >> 5;
    const int lane = tid & 31;
    const int m0 = blockIdx.y * 128;
    const int n0 = blockIdx.x * 128;
    const int wm = (wid >> 2) * 64;      // warp row offset in tile
    const int wn = (wid & 3) * 32;       // warp col offset in tile

    float acc[4][4][4];
#pragma unroll
    for (int i = 0; i < 4; i++)
#pragma unroll
        for (int j = 0; j < 4; j++)
#pragma unroll
            for (int r = 0; r < 4; r++) acc[i][j][r] = 0.0f;

    // ldmatrix lane addressing (fixed per thread)
    const int a_row = lane & 15;                        // + wm + mi*16
    const int a_ch  = lane >> 4;                        // 0/1 within k16
    const int b_row = (lane & 7) + ((lane >> 4) << 3);  // + wn + half*16
    const int b_ch  = (lane >> 3) & 1;

    // Prologue: prefetch stages 0..2
    load_stage(sb, 0, 0, A, W, m0, n0, tid);
    CP_COMMIT();
    load_stage(sb, 1, 1, A, W, m0, n0, tid);
    CP_COMMIT();
    load_stage(sb, 2, 2, A, W, m0, n0, tid);
    CP_COMMIT();

    int buf = 0;
    for (int s = 0; s < NKS; s++) {
        CP_WAIT(2);            // stage s resident
        __syncthreads();       // all warps done with the buffer we refill below

        if (s + 3 < NKS) {
            int nbuf = buf + 3; if (nbuf >= STAGES) nbuf -= STAGES;
            load_stage(sb, nbuf, s + 3, A, W, m0, n0, tid);
        }
        CP_COMMIT();           // commit (possibly empty) group to keep count in sync

        const uint32_t st = sb + buf * STAGEB;
#pragma unroll
        for (int kk = 0; kk < 2; kk++) {
            uint32_t af[4][4], bf[4][2];
#pragma unroll
            for (int mi = 0; mi < 4; mi++) {
                uint32_t aoff = sw_off(wm + mi * 16 + a_row, kk * 2 + a_ch);
                ldsm4(af[mi][0], af[mi][1], af[mi][2], af[mi][3],
                      st + 0 * TILEB + aoff);
            }
#pragma unroll
            for (int half = 0; half < 2; half++) {
                uint32_t boff = sw_off(wn + b_row + half * 16, kk * 2 + b_ch);
                ldsm4(bf[half * 2][0], bf[half * 2][1],
                      bf[half * 2 + 1][0], bf[half * 2 + 1][1],
                      st + 1 * TILEB + boff);
            }
#pragma unroll
            for (int mi = 0; mi < 4; mi++)
#pragma unroll
                for (int ni = 0; ni < 4; ni++)
                    mma16816h(acc[mi][ni], af[mi], bf[ni]);
        }
        buf++; if (buf >= STAGES) buf -= STAGES;
    }

    // Epilogue: add bias, store fp32
    const int er = lane >> 2;
    const int ec = (lane & 3) * 2;
#pragma unroll
    for (int mi = 0; mi < 4; mi++) {
        const int r = m0 + wm + mi * 16 + er;
#pragma unroll
        for (int ni = 0; ni < 4; ni++) {
            const int c = n0 + wn + ni * 8 + ec;
            const float b0 = __ldg(bias + c);
            const float b1 = __ldg(bias + c + 1);
            float2 v0 = {acc[mi][ni][0] + b0, acc[mi][ni][1] + b1};
            float2 v1 = {acc[mi][ni][2] + b0, acc[mi][ni][3] + b1};
            *reinterpret_cast<float2*>(C + (size_t)r * HIDN + c) = v0;
            *reinterpret_cast<float2*>(C + (size_t)(r + 8) * HIDN + c) = v1;
        }
    }
}

// ---------------------------------------------------------------------------
// IndRNN scan, software-pipelined prefetch (32 deep), 256 thr x 128 blocks
// (single wave). fp32 output variant for the final layer.
// ---------------------------------------------------------------------------
__global__ __launch_bounds__(256)
void indrnn_scan_f32(const float* __restrict__ lin, const float* __restrict__ rec,
                     float* __restrict__ y, float* __restrict__ hid_out, int off)
{
    const int idx = blockIdx.x * 256 + threadIdx.x;
    const int h = idx & (HIDN - 1);
    const int b = idx >> 10;
    const float r = rec[h];
    const float* p = lin + idx;
    float* q = y + idx;

    float cur[32], nxt[32];
#pragma unroll
    for (int u = 0; u < 32; u++) cur[u] = __ldcs(p + (size_t)u * BH);

    float hv = 0.0f;
    for (int s0 = 0; s0 < SEQ; s0 += 32) {
        if (s0 + 32 < SEQ) {
#pragma unroll
            for (int u = 0; u < 32; u++) nxt[u] = __ldcs(p + (size_t)(s0 + 32 + u) * BH);
        }
#pragma unroll
        for (int u = 0; u < 32; u++) {
            hv = fmaxf(fmaf(r, hv, cur[u]), 0.0f);
            q[(size_t)(s0 + u) * BH] = hv;
        }
#pragma unroll
        for (int u = 0; u < 32; u++) cur[u] = nxt[u];
    }
    hid_out[(size_t)b * (2 * HIDN) + off + h] = hv;
}

// Variant writing fp16 directly (feeds the next layer's GEMM).
__global__ __launch_bounds__(256)
void indrnn_scan_h(const float* __restrict__ lin, const float* __restrict__ rec,
                   __half* __restrict__ yh, float* __restrict__ hid_out, int off)
{
    const int idx = blockIdx.x * 256 + threadIdx.x;
    const int h = idx & (HIDN - 1);
    const int b = idx >> 10;
    const float r = rec[h];
    const float* p = lin + idx;

    float cur[32], nxt[32];
#pragma unroll
    for (int u = 0; u < 32; u++) cur[u] = __ldcs(p + (size_t)u * BH);

    float hv = 0.0f;
    for (int s0 = 0; s0 < SEQ; s0 += 32) {
        if (s0 + 32 < SEQ) {
#pragma unroll
            for (int u = 0; u < 32; u++) nxt[u] = __ldcs(p + (size_t)(s0 + 32 + u) * BH);
        }
#pragma unroll
        for (int u = 0; u < 32; u++) {
            hv = fmaxf(fmaf(r, hv, cur[u]), 0.0f);
            yh[(size_t)(s0 + u) * BH + idx] = __float2half_rn(hv);
        }
#pragma unroll
        for (int u = 0; u < 32; u++) cur[u] = nxt[u];
    }
    hid_out[(size_t)b * (2 * HIDN) + off + h] = hv;
}

// ---------------------------------------------------------------------------
// kernel_launch
// Inputs: x (S,B,IN), w0 (H,IN), b0 (H), w1 (H,H), b1 (H), rec (2,H)
// Output: y1 (S,B,H) then hiddens (B, 2H)
// ---------------------------------------------------------------------------
extern "C" void kernel_launch(void* const* d_in, const int* in_sizes, int n_in,
                              void* d_out, int out_size)
{
    const float* x   = (const float*)d_in[0];
    const float* w0  = (const float*)d_in[1];
    const float* b0  = (const float*)d_in[2];
    const float* w1  = (const float*)d_in[3];
    const float* b1  = (const float*)d_in[4];
    const float* rec = (const float*)d_in[5];

    float* out     = (float*)d_out;
    float* y1_out  = out;
    float* hid_out = out + (size_t)MTOT * HIDN;

    __half *Ah, *Wh;
    float* lin;
    cudaGetSymbolAddress((void**)&Ah, g_Ah);
    cudaGetSymbolAddress((void**)&Wh, g_Wh);
    cudaGetSymbolAddress((void**)&lin, g_lin);

    cudaFuncSetAttribute(gemm_fp16, cudaFuncAttributeMaxDynamicSharedMemorySize, GEMM_SMEM);

    const int nX4 = MTOT * KDIM / 4;
    const int nW4 = HIDN * KDIM / 4;

    dim3 ggrid(HIDN / 128, MTOT / 128);  // (8, 64)
    dim3 sgrid(BH / 256);                // 128 blocks (single wave)

    // Layer 0
    cvt_fp32_fp16<<<(nX4 + 255) / 256, 256>>>(x, Ah, nX4);
    cvt_fp32_fp16<<<(nW4 + 255) / 256, 256>>>(w0, Wh, nW4);
    gemm_fp16<<<ggrid, 256, GEMM_SMEM>>>(Ah, Wh, b0, lin);
    indrnn_scan_h<<<sgrid, 256>>>(lin, rec, Ah, hid_out, 0);

    // Layer 1
    cvt_fp32_fp16<<<(nW4 + 255) / 256, 256>>>(w1, Wh, nW4);
    gemm_fp16<<<ggrid, 256, GEMM_SMEM>>>(Ah, Wh, b1, lin);
    indrnn_scan_f32<<<sgrid, 256>>>(lin, rec + HIDN, y1_out, hid_out, HIDN);
}

// round 10
// speedup vs baseline: 7.7872x; 1.0590x over previous
#include <cuda_runtime.h>
#include <cuda_fp16.h>
#include <cstdint>

// Problem dims
#define SEQ   256
#define BATCH 32
#define HIDN  1024
#define KDIM  1024
#define MTOT  (SEQ * BATCH)        // 8192
#define BH    (BATCH * HIDN)       // 32768

// ---------------------------------------------------------------------------
// Device-global scratch (no allocation allowed)
// ---------------------------------------------------------------------------
__device__ __align__(16) __half g_Ah[MTOT * KDIM];   // 16 MB (x / y0 in fp16)
__device__ __align__(16) __half g_Wh[HIDN * KDIM];   // 2 MB
__device__ __align__(16) float  g_lin[MTOT * HIDN];  // 32 MB

// ---------------------------------------------------------------------------
// PTX helpers (base sm_103 features only: cp.async, ldmatrix, mma.sync)
// ---------------------------------------------------------------------------
__device__ __forceinline__ uint32_t smem_to_u32(const void* p) {
    uint32_t a;
    asm("{ .reg .u64 t; cvta.to.shared.u64 t, %1; cvt.u32.u64 %0, t; }" : "=r"(a) : "l"(p));
    return a;
}

__device__ __forceinline__ void cp16(uint32_t s, const void* g) {
    asm volatile("cp.async.cg.shared.global [%0], [%1], 16;" :: "r"(s), "l"(g));
}
#define CP_COMMIT() asm volatile("cp.async.commit_group;" ::: "memory")
#define CP_WAIT(n)  asm volatile("cp.async.wait_group %0;" :: "n"(n) : "memory")

__device__ __forceinline__ void ldsm4(uint32_t& r0, uint32_t& r1, uint32_t& r2,
                                      uint32_t& r3, uint32_t addr) {
    asm volatile("ldmatrix.sync.aligned.m8n8.x4.shared.b16 {%0,%1,%2,%3}, [%4];"
        : "=r"(r0), "=r"(r1), "=r"(r2), "=r"(r3) : "r"(addr));
}

__device__ __forceinline__ void mma16816h(float* c, const uint32_t* a, const uint32_t* b) {
    asm volatile(
        "mma.sync.aligned.m16n8k16.row.col.f32.f16.f16.f32 "
        "{%0,%1,%2,%3}, {%4,%5,%6,%7}, {%8,%9}, {%0,%1,%2,%3};"
        : "+f"(c[0]), "+f"(c[1]), "+f"(c[2]), "+f"(c[3])
        : "r"(a[0]), "r"(a[1]), "r"(a[2]), "r"(a[3]), "r"(b[0]), "r"(b[1]));
}

// XOR swizzle for 64B rows (4x 16B chunks): conflict-free for ldmatrix phases
// and cp.async store phases. period = 8 rows.
__device__ __forceinline__ uint32_t sw_off(int row, int ch) {
    return (uint32_t)((row << 6) + ((ch ^ ((row >> 1) & 3)) << 4));
}

// ---------------------------------------------------------------------------
// Convert fp32 -> fp16 (vectorized by 4)
// ---------------------------------------------------------------------------
__global__ __launch_bounds__(256)
void cvt_fp32_fp16(const float* __restrict__ in, __half* __restrict__ out, int n4)
{
    int i = blockIdx.x * blockDim.x + threadIdx.x;
    if (i >= n4) return;
    float4 v = reinterpret_cast<const float4*>(in)[i];
    union { __half h[4]; uint2 u; } H;
    H.h[0] = __float2half_rn(v.x);
    H.h[1] = __float2half_rn(v.y);
    H.h[2] = __float2half_rn(v.z);
    H.h[3] = __float2half_rn(v.w);
    reinterpret_cast<uint2*>(out)[i] = H.u;
}

// ---------------------------------------------------------------------------
// Single-pass fp16 mma.sync GEMM: C[m,n] = sum_k A[m,k]*W[n,k] + bias[n]
// fp32 register accumulators. CTA tile 128x128, 4 warps, warp tile 64x64.
// K-stage 32, 4-stage cp.async pipeline, XOR-swizzled smem.
// ---------------------------------------------------------------------------
#define STAGES      4
#define BKC         32
#define NKS         (KDIM / BKC)              // 32
#define TILEB       (128 * 64)                // 8192 bytes per tile
#define STAGEB      (2 * TILEB)               // 16384 (A + W)
#define GEMM_SMEM   (STAGES * STAGEB)         // 65536

__device__ __forceinline__ void load_stage(uint32_t sb, int buf, int s,
                                           const __half* __restrict__ A,
                                           const __half* __restrict__ W,
                                           int m0, int n0, int tid)
{
    const int kc = s * BKC;
    const uint32_t base = sb + buf * STAGEB;
#pragma unroll
    for (int it = 0; it < 4; it++) {
        int t = tid + it * 128;          // 0..511 -> 128 rows x 4 chunks
        int row = t >> 2;
        int ch = t & 3;
        uint32_t soff = sw_off(row, ch);
        cp16(base + 0 * TILEB + soff, A + (size_t)(m0 + row) * KDIM + kc + ch * 8);
        cp16(base + 1 * TILEB + soff, W + (size_t)(n0 + row) * KDIM + kc + ch * 8);
    }
}

__global__ __launch_bounds__(128, 2)
void gemm_fp16(const __half* __restrict__ A,
               const __half* __restrict__ W,
               const float* __restrict__ bias,
               float* __restrict__ C)
{
    extern __shared__ __align__(16) char smem[];
    const uint32_t sb = smem_to_u32(smem);
    const int tid = threadIdx.x;
    const int wid = tid >> 5;
    const int lane = tid & 31;
    const int m0 = blockIdx.y * 128;
    const int n0 = blockIdx.x * 128;
    const int wm = (wid >> 1) * 64;      // warp row offset in tile
    const int wn = (wid & 1) * 64;       // warp col offset in tile

    float acc[4][8][4];
#pragma unroll
    for (int i = 0; i < 4; i++)
#pragma unroll
        for (int j = 0; j < 8; j++)
#pragma unroll
            for (int r = 0; r < 4; r++) acc[i][j][r] = 0.0f;

    // ldmatrix lane addressing (fixed per thread)
    const int a_row = lane & 15;                        // + wm + mi*16
    const int a_ch  = lane >> 4;                        // 0/1 within k16
    const int b_row = (lane & 7) + ((lane >> 4) << 3);  // + wn + half*16
    const int b_ch  = (lane >> 3) & 1;

    // Prologue: prefetch stages 0..2
    load_stage(sb, 0, 0, A, W, m0, n0, tid);
    CP_COMMIT();
    load_stage(sb, 1, 1, A, W, m0, n0, tid);
    CP_COMMIT();
    load_stage(sb, 2, 2, A, W, m0, n0, tid);
    CP_COMMIT();

    int buf = 0;
    for (int s = 0; s < NKS; s++) {
        CP_WAIT(2);            // stage s resident
        __syncthreads();       // all warps done with the buffer we refill below

        if (s + 3 < NKS) {
            int nbuf = buf + 3; if (nbuf >= STAGES) nbuf -= STAGES;
            load_stage(sb, nbuf, s + 3, A, W, m0, n0, tid);
        }
        CP_COMMIT();           // commit (possibly empty) group to keep count in sync

        const uint32_t st = sb + buf * STAGEB;
#pragma unroll
        for (int kk = 0; kk < 2; kk++) {
            uint32_t af[4][4], bf[8][2];
#pragma unroll
            for (int mi = 0; mi < 4; mi++) {
                uint32_t aoff = sw_off(wm + mi * 16 + a_row, kk * 2 + a_ch);
                ldsm4(af[mi][0], af[mi][1], af[mi][2], af[mi][3],
                      st + 0 * TILEB + aoff);
            }
#pragma unroll
            for (int half = 0; half < 4; half++) {
                uint32_t boff = sw_off(wn + b_row + half * 16, kk * 2 + b_ch);
                ldsm4(bf[half * 2][0], bf[half * 2][1],
                      bf[half * 2 + 1][0], bf[half * 2 + 1][1],
                      st + 1 * TILEB + boff);
            }
#pragma unroll
            for (int mi = 0; mi < 4; mi++)
#pragma unroll
                for (int ni = 0; ni < 8; ni++)
                    mma16816h(acc[mi][ni], af[mi], bf[ni]);
        }
        buf++; if (buf >= STAGES) buf -= STAGES;
    }

    // Epilogue: add bias, store fp32
    const int er = lane >> 2;
    const int ec = (lane & 3) * 2;
#pragma unroll
    for (int mi = 0; mi < 4; mi++) {
        const int r = m0 + wm + mi * 16 + er;
#pragma unroll
        for (int ni = 0; ni < 8; ni++) {
            const int c = n0 + wn + ni * 8 + ec;
            const float b0 = __ldg(bias + c);
            const float b1 = __ldg(bias + c + 1);
            float2 v0 = {acc[mi][ni][0] + b0, acc[mi][ni][1] + b1};
            float2 v1 = {acc[mi][ni][2] + b0, acc[mi][ni][3] + b1};
            *reinterpret_cast<float2*>(C + (size_t)r * HIDN + c) = v0;
            *reinterpret_cast<float2*>(C + (size_t)(r + 8) * HIDN + c) = v1;
        }
    }
}

// ---------------------------------------------------------------------------
// IndRNN scan, software-pipelined prefetch (32 deep), 256 thr x 128 blocks.
// fp32 output variant for the final layer.
// ---------------------------------------------------------------------------
__global__ __launch_bounds__(256)
void indrnn_scan_f32(const float* __restrict__ lin, const float* __restrict__ rec,
                     float* __restrict__ y, float* __restrict__ hid_out, int off)
{
    const int idx = blockIdx.x * 256 + threadIdx.x;
    const int h = idx & (HIDN - 1);
    const int b = idx >> 10;
    const float r = rec[h];
    const float* p = lin + idx;
    float* q = y + idx;

    float cur[32], nxt[32];
#pragma unroll
    for (int u = 0; u < 32; u++) cur[u] = __ldcs(p + (size_t)u * BH);

    float hv = 0.0f;
    for (int s0 = 0; s0 < SEQ; s0 += 32) {
        if (s0 + 32 < SEQ) {
#pragma unroll
            for (int u = 0; u < 32; u++) nxt[u] = __ldcs(p + (size_t)(s0 + 32 + u) * BH);
        }
#pragma unroll
        for (int u = 0; u < 32; u++) {
            hv = fmaxf(fmaf(r, hv, cur[u]), 0.0f);
            q[(size_t)(s0 + u) * BH] = hv;
        }
#pragma unroll
        for (int u = 0; u < 32; u++) cur[u] = nxt[u];
    }
    hid_out[(size_t)b * (2 * HIDN) + off + h] = hv;
}

// Variant writing fp16 directly (feeds the next layer's GEMM).
__global__ __launch_bounds__(256)
void indrnn_scan_h(const float* __restrict__ lin, const float* __restrict__ rec,
                   __half* __restrict__ yh, float* __restrict__ hid_out, int off)
{
    const int idx = blockIdx.x * 256 + threadIdx.x;
    const int h = idx & (HIDN - 1);
    const int b = idx >> 10;
    const float r = rec[h];
    const float* p = lin + idx;

    float cur[32], nxt[32];
#pragma unroll
    for (int u = 0; u < 32; u++) cur[u] = __ldcs(p + (size_t)u * BH);

    float hv = 0.0f;
    for (int s0 = 0; s0 < SEQ; s0 += 32) {
        if (s0 + 32 < SEQ) {
#pragma unroll
            for (int u = 0; u < 32; u++) nxt[u] = __ldcs(p + (size_t)(s0 + 32 + u) * BH);
        }
#pragma unroll
        for (int u = 0; u < 32; u++) {
            hv = fmaxf(fmaf(r, hv, cur[u]), 0.0f);
            yh[(size_t)(s0 + u) * BH + idx] = __float2half_rn(hv);
        }
#pragma unroll
        for (int u = 0; u < 32; u++) cur[u] = nxt[u];
    }
    hid_out[(size_t)b * (2 * HIDN) + off + h] = hv;
}

// ---------------------------------------------------------------------------
// kernel_launch
// Inputs: x (S,B,IN), w0 (H,IN), b0 (H), w1 (H,H), b1 (H), rec (2,H)
// Output: y1 (S,B,H) then hiddens (B, 2H)
// ---------------------------------------------------------------------------
extern "C" void kernel_launch(void* const* d_in, const int* in_sizes, int n_in,
                              void* d_out, int out_size)
{
    const float* x   = (const float*)d_in[0];
    const float* w0  = (const float*)d_in[1];
    const float* b0  = (const float*)d_in[2];
    const float* w1  = (const float*)d_in[3];
    const float* b1  = (const float*)d_in[4];
    const float* rec = (const float*)d_in[5];

    float* out     = (float*)d_out;
    float* y1_out  = out;
    float* hid_out = out + (size_t)MTOT * HIDN;

    __half *Ah, *Wh;
    float* lin;
    cudaGetSymbolAddress((void**)&Ah, g_Ah);
    cudaGetSymbolAddress((void**)&Wh, g_Wh);
    cudaGetSymbolAddress((void**)&lin, g_lin);

    cudaFuncSetAttribute(gemm_fp16, cudaFuncAttributeMaxDynamicSharedMemorySize, GEMM_SMEM);

    const int nX4 = MTOT * KDIM / 4;
    const int nW4 = HIDN * KDIM / 4;

    dim3 ggrid(HIDN / 128, MTOT / 128);  // (8, 64)
    dim3 sgrid(BH / 256);                // 128 blocks

    // Layer 0
    cvt_fp32_fp16<<<(nX4 + 255) / 256, 256>>>(x, Ah, nX4);
    cvt_fp32_fp16<<<(nW4 + 255) / 256, 256>>>(w0, Wh, nW4);
    gemm_fp16<<<ggrid, 128, GEMM_SMEM>>>(Ah, Wh, b0, lin);
    indrnn_scan_h<<<sgrid, 256>>>(lin, rec, Ah, hid_out, 0);

    // Layer 1
    cvt_fp32_fp16<<<(nW4 + 255) / 256, 256>>>(w1, Wh, nW4);
    gemm_fp16<<<ggrid, 128, GEMM_SMEM>>>(Ah, Wh, b1, lin);
    indrnn_scan_f32<<<sgrid, 256>>>(lin, rec + HIDN, y1_out, hid_out, HIDN);
}